// round 4
// baseline (speedup 1.0000x reference)
#include <cuda_runtime.h>
#include <math.h>

#define S_DIM 512
#define N_DIM 384
#define CIN   64
#define CZ    128
#define H_DIM 8
#define C_DIM 32
#define D_DIM 256
#define INF_  1e9f
#define EPS_  1e-5f
#define MROWS (S_DIM*N_DIM)   // 196608

// ---- scratch (static device arrays: no allocations allowed) ----
__device__ float g_w [(size_t)H_DIM*N_DIM*N_DIM];          // attn weights [h][q][k]
__device__ float g_mn[(size_t)MROWS*CIN];                   // LN(m)
__device__ float g_v [(size_t)H_DIM*N_DIM*S_DIM*C_DIM];     // v  [h][k][s][c]
__device__ float g_g [(size_t)MROWS*D_DIM];                 // gate [s*N+n][256]
__device__ float g_o [(size_t)MROWS*D_DIM];                 // o    [s*N+q][256]

// ============================================================
// Kernel 1: LN(z) + logits (warp per (q,k) row of 128)
// ============================================================
__global__ void k_lnz_logits(const float* __restrict__ z, const float* __restrict__ mask,
                             const float* __restrict__ gamma_z, const float* __restrict__ beta_z,
                             const float* __restrict__ w_z, const float* __restrict__ b_z)
{
    int gw   = (blockIdx.x * blockDim.x + threadIdx.x) >> 5;
    int lane = threadIdx.x & 31;
    if (gw >= N_DIM * N_DIM) return;
    int q = gw / N_DIM, k = gw % N_DIM;
    const float* zp = z + (size_t)gw * CZ;

    float x0 = zp[lane], x1 = zp[lane+32], x2 = zp[lane+64], x3 = zp[lane+96];
    float s  = x0+x1+x2+x3;
    float s2 = x0*x0 + x1*x1 + x2*x2 + x3*x3;
    #pragma unroll
    for (int o = 16; o; o >>= 1) {
        s  += __shfl_xor_sync(0xffffffffu, s,  o);
        s2 += __shfl_xor_sync(0xffffffffu, s2, o);
    }
    float mu  = s * (1.0f / CZ);
    float inv = rsqrtf(s2 * (1.0f / CZ) - mu*mu + EPS_);
    float n0 = (x0-mu)*inv*gamma_z[lane]    + beta_z[lane];
    float n1 = (x1-mu)*inv*gamma_z[lane+32] + beta_z[lane+32];
    float n2 = (x2-mu)*inv*gamma_z[lane+64] + beta_z[lane+64];
    float n3 = (x3-mu)*inv*gamma_z[lane+96] + beta_z[lane+96];

    float acc[H_DIM];
    #pragma unroll
    for (int h = 0; h < H_DIM; h++) {
        acc[h] = n0 * w_z[lane*H_DIM + h]
               + n1 * w_z[(lane+32)*H_DIM + h]
               + n2 * w_z[(lane+64)*H_DIM + h]
               + n3 * w_z[(lane+96)*H_DIM + h];
        #pragma unroll
        for (int o = 16; o; o >>= 1)
            acc[h] += __shfl_xor_sync(0xffffffffu, acc[h], o);
    }
    if (lane == 0) {
        float bias = INF_ * (mask[gw] - 1.0f);
        #pragma unroll
        for (int h = 0; h < H_DIM; h++)
            g_w[((size_t)h*N_DIM + q)*N_DIM + k] = acc[h] + b_z[h] + bias;
    }
}

// ============================================================
// Kernel 2: softmax over k for each (h,q) row (in place in g_w)
// ============================================================
__global__ void k_softmax()
{
    int row = blockIdx.x;
    float* p = g_w + (size_t)row * N_DIM;
    int tid = threadIdx.x;  // 128 threads, 3 elems each
    __shared__ float red[128];

    float v0 = p[tid], v1 = p[tid+128], v2 = p[tid+256];
    float mx = fmaxf(v0, fmaxf(v1, v2));
    red[tid] = mx; __syncthreads();
    for (int o = 64; o; o >>= 1) { if (tid < o) red[tid] = fmaxf(red[tid], red[tid+o]); __syncthreads(); }
    mx = red[0]; __syncthreads();

    float e0 = expf(v0-mx), e1 = expf(v1-mx), e2 = expf(v2-mx);
    red[tid] = e0 + e1 + e2; __syncthreads();
    for (int o = 64; o; o >>= 1) { if (tid < o) red[tid] += red[tid+o]; __syncthreads(); }
    float inv = 1.0f / red[0];

    p[tid] = e0*inv; p[tid+128] = e1*inv; p[tid+256] = e2*inv;
}

// ============================================================
// Kernel 3: LN(m) -> g_mn (warp per row of 64)
// ============================================================
__global__ void k_lnm(const float* __restrict__ m,
                      const float* __restrict__ gamma_m, const float* __restrict__ beta_m)
{
    int gw   = (blockIdx.x * blockDim.x + threadIdx.x) >> 5;
    int lane = threadIdx.x & 31;
    if (gw >= MROWS) return;
    const float* mp = m + (size_t)gw * CIN;
    float a = mp[lane], b = mp[lane+32];
    float s = a + b, s2 = a*a + b*b;
    #pragma unroll
    for (int o = 16; o; o >>= 1) {
        s  += __shfl_xor_sync(0xffffffffu, s,  o);
        s2 += __shfl_xor_sync(0xffffffffu, s2, o);
    }
    float mu  = s * (1.0f / CIN);
    float inv = rsqrtf(s2 * (1.0f / CIN) - mu*mu + EPS_);
    float* op = g_mn + (size_t)gw * CIN;
    op[lane]    = (a-mu)*inv*gamma_m[lane]    + beta_m[lane];
    op[lane+32] = (b-mu)*inv*gamma_m[lane+32] + beta_m[lane+32];
}

// ============================================================
// Kernel 4: GEMM mn[196608,64] @ [w_v | w_g][64,512]
//   epilogue: j<256 -> +b_v, scatter to g_v[h][k][s][c]
//             j>=256 -> sigmoid(+b_g) -> g_g[row][j-256]
// ============================================================
__global__ __launch_bounds__(256) void k_gemm_vg(const float* __restrict__ w_v, const float* __restrict__ b_v,
                                                 const float* __restrict__ w_g, const float* __restrict__ b_g)
{
    const int BM = 128, BN = 64, BK = 16;
    __shared__ __align__(16) float As[BK][BM];
    __shared__ __align__(16) float Bs[BK][BN];
    int tid = threadIdx.x;
    int tx  = tid & 15, ty = tid >> 4;
    int m0  = blockIdx.y * BM;
    int n0  = blockIdx.x * BN;
    int ar  = tid >> 2, ac = (tid & 3) * 4;
    int br  = tid >> 4, bc = (tid & 15) * 4;
    float acc[8][4] = {};

    for (int k0 = 0; k0 < CIN; k0 += BK) {
        #pragma unroll
        for (int half = 0; half < BM; half += 64) {
            float4 av = *(const float4*)(g_mn + (size_t)(m0+ar+half)*CIN + k0 + ac);
            As[ac+0][ar+half] = av.x; As[ac+1][ar+half] = av.y;
            As[ac+2][ar+half] = av.z; As[ac+3][ar+half] = av.w;
        }
        #pragma unroll
        for (int u = 0; u < 4; u++) {
            int j = n0 + bc + u;
            Bs[br][bc+u] = (j < D_DIM) ? w_v[(k0+br)*D_DIM + j]
                                       : w_g[(k0+br)*D_DIM + (j - D_DIM)];
        }
        __syncthreads();
        #pragma unroll
        for (int kk = 0; kk < BK; kk++) {
            float rA[8], rB[4];
            #pragma unroll
            for (int i = 0; i < 8; i++) rA[i] = As[kk][ty*8+i];
            #pragma unroll
            for (int j = 0; j < 4; j++) rB[j] = Bs[kk][tx*4+j];
            #pragma unroll
            for (int i = 0; i < 8; i++)
                #pragma unroll
                for (int j = 0; j < 4; j++)
                    acc[i][j] += rA[i] * rB[j];
        }
        __syncthreads();
    }

    #pragma unroll
    for (int i = 0; i < 8; i++) {
        int row = m0 + ty*8 + i;
        int sI = row / N_DIM, kI = row % N_DIM;   // row = s*N + n
        #pragma unroll
        for (int j = 0; j < 4; j++) {
            int col = n0 + tx*4 + j;
            if (col < D_DIM) {
                float val = acc[i][j] + b_v[col];
                g_v[(((size_t)(col >> 5)*N_DIM + kI)*S_DIM + sI)*C_DIM + (col & 31)] = val;
            } else {
                int jg = col - D_DIM;
                float t = acc[i][j] + b_g[jg];
                g_g[(size_t)row*D_DIM + jg] = 1.0f / (1.0f + expf(-t));
            }
        }
    }
}

// ============================================================
// Kernel 5: per-head GEMM  w_h[384,384] @ v_h[384,16384] -> o
//   epilogue scatter: g_o[(s*N+q)*256 + h*32 + c]
// ============================================================
__global__ __launch_bounds__(256) void k_gemm_att()
{
    const int BM = 128, BN = 64, BK = 16;
    __shared__ __align__(16) float As[BK][BM];
    __shared__ __align__(16) float Bs[BK][BN];
    int tid = threadIdx.x;
    int tx  = tid & 15, ty = tid >> 4;
    int h   = blockIdx.z;
    int m0  = blockIdx.y * BM;     // q tile (M=384)
    int n0  = blockIdx.x * BN;     // n tile (N=16384)
    const float* A = g_w + (size_t)h * N_DIM * N_DIM;
    const float* B = g_v + (size_t)h * N_DIM * S_DIM * C_DIM;
    const int lda = N_DIM, ldb = S_DIM * C_DIM;
    int ar = tid >> 2, ac = (tid & 3) * 4;
    int br = tid >> 4, bc = (tid & 15) * 4;
    float acc[8][4] = {};

    for (int k0 = 0; k0 < N_DIM; k0 += BK) {
        #pragma unroll
        for (int half = 0; half < BM; half += 64) {
            float4 av = *(const float4*)(A + (size_t)(m0+ar+half)*lda + k0 + ac);
            As[ac+0][ar+half] = av.x; As[ac+1][ar+half] = av.y;
            As[ac+2][ar+half] = av.z; As[ac+3][ar+half] = av.w;
        }
        float4 bv = *(const float4*)(B + (size_t)(k0+br)*ldb + n0 + bc);
        *(float4*)&Bs[br][bc] = bv;
        __syncthreads();
        #pragma unroll
        for (int kk = 0; kk < BK; kk++) {
            float rA[8], rB[4];
            #pragma unroll
            for (int i = 0; i < 8; i++) rA[i] = As[kk][ty*8+i];
            #pragma unroll
            for (int j = 0; j < 4; j++) rB[j] = Bs[kk][tx*4+j];
            #pragma unroll
            for (int i = 0; i < 8; i++)
                #pragma unroll
                for (int j = 0; j < 4; j++)
                    acc[i][j] += rA[i] * rB[j];
        }
        __syncthreads();
    }

    #pragma unroll
    for (int i = 0; i < 8; i++) {
        int q = m0 + ty*8 + i;
        #pragma unroll
        for (int j = 0; j < 4; j++) {
            int n  = n0 + tx*4 + j;
            int sI = n >> 5, c = n & 31;
            g_o[((size_t)sI*N_DIM + q)*D_DIM + h*C_DIM + c] = acc[i][j];
        }
    }
}

// ============================================================
// Kernel 6: GEMM (o*g)[196608,256] @ w_o[256,64] + b_o -> out
//   gating fused into the A-tile load
// ============================================================
__global__ __launch_bounds__(256) void k_gemm_out(const float* __restrict__ w_o,
                                                  const float* __restrict__ b_o,
                                                  float* __restrict__ out)
{
    const int BM = 128, BN = 64, BK = 16;
    __shared__ __align__(16) float As[BK][BM];
    __shared__ __align__(16) float Bs[BK][BN];
    int tid = threadIdx.x;
    int tx  = tid & 15, ty = tid >> 4;
    int m0  = blockIdx.y * BM;
    int ar  = tid >> 2, ac = (tid & 3) * 4;
    int br  = tid >> 4, bc = (tid & 15) * 4;
    float acc[8][4] = {};

    for (int k0 = 0; k0 < D_DIM; k0 += BK) {
        #pragma unroll
        for (int half = 0; half < BM; half += 64) {
            size_t base = (size_t)(m0+ar+half)*D_DIM + k0 + ac;
            float4 ao = *(const float4*)(g_o + base);
            float4 ag = *(const float4*)(g_g + base);
            As[ac+0][ar+half] = ao.x*ag.x; As[ac+1][ar+half] = ao.y*ag.y;
            As[ac+2][ar+half] = ao.z*ag.z; As[ac+3][ar+half] = ao.w*ag.w;
        }
        float4 bv = *(const float4*)(w_o + (k0+br)*BN + bc);
        *(float4*)&Bs[br][bc] = bv;
        __syncthreads();
        #pragma unroll
        for (int kk = 0; kk < BK; kk++) {
            float rA[8], rB[4];
            #pragma unroll
            for (int i = 0; i < 8; i++) rA[i] = As[kk][ty*8+i];
            #pragma unroll
            for (int j = 0; j < 4; j++) rB[j] = Bs[kk][tx*4+j];
            #pragma unroll
            for (int i = 0; i < 8; i++)
                #pragma unroll
                for (int j = 0; j < 4; j++)
                    acc[i][j] += rA[i] * rB[j];
        }
        __syncthreads();
    }

    #pragma unroll
    for (int i = 0; i < 8; i++) {
        int row = m0 + ty*8 + i;
        #pragma unroll
        for (int j = 0; j < 4; j++) {
            int col = tx*4 + j;
            out[(size_t)row*CIN + col] = acc[i][j] + b_o[col];
        }
    }
}

// ============================================================
extern "C" void kernel_launch(void* const* d_in, const int* in_sizes, int n_in,
                              void* d_out, int out_size)
{
    const float* m       = (const float*)d_in[0];
    const float* z       = (const float*)d_in[1];
    const float* mask    = (const float*)d_in[2];
    const float* gamma_m = (const float*)d_in[3];
    const float* beta_m  = (const float*)d_in[4];
    const float* gamma_z = (const float*)d_in[5];
    const float* beta_z  = (const float*)d_in[6];
    const float* w_z     = (const float*)d_in[7];
    const float* b_z     = (const float*)d_in[8];
    const float* w_v     = (const float*)d_in[9];
    const float* b_v     = (const float*)d_in[10];
    const float* w_g     = (const float*)d_in[11];
    const float* b_g     = (const float*)d_in[12];
    const float* w_o     = (const float*)d_in[13];
    const float* b_o     = (const float*)d_in[14];
    float* out = (float*)d_out;

    // 1. LN(z) + logits: 147456 (q,k) warps, 8 warps/block
    k_lnz_logits<<<(N_DIM*N_DIM)/8, 256>>>(z, mask, gamma_z, beta_z, w_z, b_z);
    // 2. softmax over k, one block per (h,q)
    k_softmax<<<H_DIM*N_DIM, 128>>>();
    // 3. LN(m): 196608 warps, 8 warps/block
    k_lnm<<<MROWS/8, 256>>>(m, gamma_m, beta_m);
    // 4. v/g projection GEMM: N=512 (8 tiles of 64), M=196608 (1536 tiles of 128)
    k_gemm_vg<<<dim3(8, MROWS/128), 256>>>(w_v, b_v, w_g, b_g);
    // 5. attention GEMM per head: N=16384 (256), M=384 (3), H=8
    k_gemm_att<<<dim3(256, 3, 8), 256>>>();
    // 6. gated output projection: N=64 (1 tile), M=196608 (1536)
    k_gemm_out<<<dim3(1, MROWS/128), 256>>>(w_o, b_o, out);
}

// round 9
// speedup vs baseline: 1.5178x; 1.5178x over previous
#include <cuda_runtime.h>
#include <cuda_bf16.h>
#include <math.h>
#include <stdint.h>

#define S_DIM 512
#define N_DIM 384
#define CIN   64
#define CZ    128
#define H_DIM 8
#define C_DIM 32
#define D_DIM 256
#define INF_  1e9f
#define EPS_  1e-5f
#define MROWS (S_DIM*N_DIM)   // 196608
#define NKC   6               // K chunks of 64 covering K=384

// ---- scratch (static device arrays: no allocations allowed) ----
__device__ float g_w [(size_t)H_DIM*N_DIM*N_DIM];   // logits [h][q][k]
__device__ float g_mn[(size_t)MROWS*CIN];           // LN(m)
__device__ float g_g [(size_t)MROWS*D_DIM];         // gate (fp32)
__device__ float g_o [(size_t)MROWS*D_DIM];         // attention output (fp32)
// split-bf16 k-major staging tiles, 128 rows x 64 k each (8192 elems, 16KB)
// w: [h][qt(3)][kc(6)]   v: [h][nt(128)][kc(6)]
__device__ __align__(1024) __nv_bfloat16 g_wh[(size_t)H_DIM*3*NKC*8192];
__device__ __align__(1024) __nv_bfloat16 g_wl[(size_t)H_DIM*3*NKC*8192];
__device__ __align__(1024) __nv_bfloat16 g_vh[(size_t)H_DIM*128*NKC*8192];
__device__ __align__(1024) __nv_bfloat16 g_vl[(size_t)H_DIM*128*NKC*8192];

// ============================================================
// helpers (Ampere-class ISA only: valid on base sm_103 target)
// ============================================================
__device__ __forceinline__ uint32_t smem_u32(const void* p){
    uint32_t a;
    asm("{ .reg .u64 t; cvta.to.shared.u64 t, %1; cvt.u32.u64 %0, t; }" : "=r"(a) : "l"(p));
    return a;
}
#define LDSM_X4(r0,r1,r2,r3,addr) \
    asm volatile("ldmatrix.sync.aligned.m8n8.x4.shared.b16 {%0,%1,%2,%3}, [%4];" \
        : "=r"(r0),"=r"(r1),"=r"(r2),"=r"(r3) : "r"(addr))
__device__ __forceinline__ void mma_bf16(float* c, const uint32_t* a, const uint32_t* b){
    asm volatile("mma.sync.aligned.m16n8k16.row.col.f32.bf16.bf16.f32 "
        "{%0,%1,%2,%3}, {%4,%5,%6,%7}, {%8,%9}, {%0,%1,%2,%3};"
        : "+f"(c[0]),"+f"(c[1]),"+f"(c[2]),"+f"(c[3])
        : "r"(a[0]),"r"(a[1]),"r"(a[2]),"r"(a[3]), "r"(b[0]),"r"(b[1]));
}
__device__ __forceinline__ void cpasync16(uint32_t dst, const void* src){
    asm volatile("cp.async.cg.shared.global [%0], [%1], 16;" :: "r"(dst), "l"(src));
}

// ============================================================
// Kernel 1: LN(z) + logits (warp per (q,k) row)
// ============================================================
__global__ void k_lnz_logits(const float* __restrict__ z, const float* __restrict__ mask,
                             const float* __restrict__ gamma_z, const float* __restrict__ beta_z,
                             const float* __restrict__ w_z, const float* __restrict__ b_z)
{
    int gw   = (blockIdx.x * blockDim.x + threadIdx.x) >> 5;
    int lane = threadIdx.x & 31;
    if (gw >= N_DIM * N_DIM) return;
    int q = gw / N_DIM, k = gw % N_DIM;
    const float* zp = z + (size_t)gw * CZ;

    float x0 = zp[lane], x1 = zp[lane+32], x2 = zp[lane+64], x3 = zp[lane+96];
    float s  = x0+x1+x2+x3;
    float s2 = x0*x0 + x1*x1 + x2*x2 + x3*x3;
    #pragma unroll
    for (int o = 16; o; o >>= 1) {
        s  += __shfl_xor_sync(0xffffffffu, s,  o);
        s2 += __shfl_xor_sync(0xffffffffu, s2, o);
    }
    float mu  = s * (1.0f / CZ);
    float inv = rsqrtf(s2 * (1.0f / CZ) - mu*mu + EPS_);
    float n0 = (x0-mu)*inv*gamma_z[lane]    + beta_z[lane];
    float n1 = (x1-mu)*inv*gamma_z[lane+32] + beta_z[lane+32];
    float n2 = (x2-mu)*inv*gamma_z[lane+64] + beta_z[lane+64];
    float n3 = (x3-mu)*inv*gamma_z[lane+96] + beta_z[lane+96];

    float acc[H_DIM];
    #pragma unroll
    for (int h = 0; h < H_DIM; h++) {
        acc[h] = n0 * w_z[lane*H_DIM + h]
               + n1 * w_z[(lane+32)*H_DIM + h]
               + n2 * w_z[(lane+64)*H_DIM + h]
               + n3 * w_z[(lane+96)*H_DIM + h];
        #pragma unroll
        for (int o = 16; o; o >>= 1)
            acc[h] += __shfl_xor_sync(0xffffffffu, acc[h], o);
    }
    if (lane == 0) {
        float bias = INF_ * (mask[gw] - 1.0f);
        #pragma unroll
        for (int h = 0; h < H_DIM; h++)
            g_w[((size_t)h*N_DIM + q)*N_DIM + k] = acc[h] + b_z[h] + bias;
    }
}

// ============================================================
// Kernel 2: softmax per (h,q) row -> split-bf16 staging (k-major)
// ============================================================
__global__ void k_softmax()
{
    int row = blockIdx.x;                   // h*384 + q
    int h = row / N_DIM, q = row - h*N_DIM;
    const float* p = g_w + (size_t)row * N_DIM;
    int tid = threadIdx.x;                  // 128 threads, 3 elems each
    __shared__ float red[128];

    float v0 = p[tid], v1 = p[tid+128], v2 = p[tid+256];
    float mx = fmaxf(v0, fmaxf(v1, v2));
    red[tid] = mx; __syncthreads();
    for (int o = 64; o; o >>= 1) { if (tid < o) red[tid] = fmaxf(red[tid], red[tid+o]); __syncthreads(); }
    mx = red[0]; __syncthreads();

    float e0 = expf(v0-mx), e1 = expf(v1-mx), e2 = expf(v2-mx);
    red[tid] = e0 + e1 + e2; __syncthreads();
    for (int o = 64; o; o >>= 1) { if (tid < o) red[tid] += red[tid+o]; __syncthreads(); }
    float inv = 1.0f / red[0];

    int r = q & 127;
    size_t blkbase = (size_t)((h*3 + (q >> 7)) * NKC);
    float ev[3] = {e0, e1, e2};
    #pragma unroll
    for (int t = 0; t < 3; t++) {
        int k = tid + t*128;
        float wv = ev[t] * inv;
        __nv_bfloat16 hi = __float2bfloat16(wv);
        __nv_bfloat16 lo = __float2bfloat16(wv - __bfloat162float(hi));
        int kc = k >> 6, kk = k & 63;
        size_t off = (blkbase + kc) * 8192 + (size_t)(r*64 + kk);
        g_wh[off] = hi;
        g_wl[off] = lo;
    }
}

// ============================================================
// Kernel 3: LN(m) -> g_mn (warp per row of 64)
// ============================================================
__global__ void k_lnm(const float* __restrict__ m,
                      const float* __restrict__ gamma_m, const float* __restrict__ beta_m)
{
    int gw   = (blockIdx.x * blockDim.x + threadIdx.x) >> 5;
    int lane = threadIdx.x & 31;
    if (gw >= MROWS) return;
    const float* mp = m + (size_t)gw * CIN;
    float a = mp[lane], b = mp[lane+32];
    float s = a + b, s2 = a*a + b*b;
    #pragma unroll
    for (int o = 16; o; o >>= 1) {
        s  += __shfl_xor_sync(0xffffffffu, s,  o);
        s2 += __shfl_xor_sync(0xffffffffu, s2, o);
    }
    float mu  = s * (1.0f / CIN);
    float inv = rsqrtf(s2 * (1.0f / CIN) - mu*mu + EPS_);
    float* op = g_mn + (size_t)gw * CIN;
    op[lane]    = (a-mu)*inv*gamma_m[lane]    + beta_m[lane];
    op[lane+32] = (b-mu)*inv*gamma_m[lane+32] + beta_m[lane+32];
}

// ============================================================
// Kernel 4: GEMM mn[196608,64] @ [w_v | w_g][64,512]
//   v cols -> smem transpose -> split-bf16 staging [h][nt][kc]
//   gate cols -> sigmoid -> g_g (fp32)
// ============================================================
__global__ __launch_bounds__(256) void k_gemm_vg(const float* __restrict__ w_v, const float* __restrict__ b_v,
                                                 const float* __restrict__ w_g, const float* __restrict__ b_g)
{
    const int BM = 128, BN = 64, BK = 16;
    __shared__ __align__(16) float As[BK][BM];
    __shared__ __align__(16) float Bs[BK][BN];
    __shared__ float T[64*129];             // transposed v tile [col][row], padded
    int tid = threadIdx.x;
    int tx  = tid & 15, ty = tid >> 4;
    int m0  = blockIdx.y * BM;
    int n0  = blockIdx.x * BN;
    int ar  = tid >> 2, ac = (tid & 3) * 4;
    int br  = tid >> 4, bc = (tid & 15) * 4;
    float acc[8][4] = {};

    for (int k0 = 0; k0 < CIN; k0 += BK) {
        #pragma unroll
        for (int half = 0; half < BM; half += 64) {
            float4 av = *(const float4*)(g_mn + (size_t)(m0+ar+half)*CIN + k0 + ac);
            As[ac+0][ar+half] = av.x; As[ac+1][ar+half] = av.y;
            As[ac+2][ar+half] = av.z; As[ac+3][ar+half] = av.w;
        }
        #pragma unroll
        for (int u = 0; u < 4; u++) {
            int j = n0 + bc + u;
            Bs[br][bc+u] = (j < D_DIM) ? w_v[(k0+br)*D_DIM + j]
                                       : w_g[(k0+br)*D_DIM + (j - D_DIM)];
        }
        __syncthreads();
        #pragma unroll
        for (int kk = 0; kk < BK; kk++) {
            float rA[8], rB[4];
            #pragma unroll
            for (int i = 0; i < 8; i++) rA[i] = As[kk][ty*8+i];
            #pragma unroll
            for (int j = 0; j < 4; j++) rB[j] = Bs[kk][tx*4+j];
            #pragma unroll
            for (int i = 0; i < 8; i++)
                #pragma unroll
                for (int j = 0; j < 4; j++)
                    acc[i][j] += rA[i] * rB[j];
        }
        __syncthreads();
    }

    if (n0 < D_DIM) {
        // ---- v block: transpose via smem, emit split-bf16 k-major tiles ----
        #pragma unroll
        for (int i = 0; i < 8; i++)
            #pragma unroll
            for (int j = 0; j < 4; j++)
                T[(tx*4+j)*129 + (ty*8+i)] = acc[i][j] + b_v[n0 + tx*4 + j];
        __syncthreads();

        int sI  = m0 / N_DIM;          // 128-row blocks never straddle s
        int kb  = m0 - sI * N_DIM;     // 0,128,256  (attention-k base)
        int kc0 = kb >> 6;
        int nt  = sI >> 2;
        int warp = tid >> 5, lane = tid & 31;
        for (int ridx = warp; ridx < 128; ridx += 8) {
            int j   = ridx >> 1, kcl = ridx & 1;
            int h   = (n0 + j) >> 5;
            int c   = (n0 + j) & 31;
            int nr  = ((sI & 3) << 5) + c;
            int kc  = kc0 + kcl;
            size_t blk = ((size_t)(h*128 + nt)*NKC + kc) * 8192;  // elems
            float f0 = T[j*129 + kcl*64 + lane*2];
            float f1 = T[j*129 + kcl*64 + lane*2 + 1];
            __nv_bfloat16 h0 = __float2bfloat16(f0);
            __nv_bfloat16 h1 = __float2bfloat16(f1);
            __nv_bfloat16 l0 = __float2bfloat16(f0 - __bfloat162float(h0));
            __nv_bfloat16 l1 = __float2bfloat16(f1 - __bfloat162float(h1));
            size_t off = blk + (size_t)nr*64 + lane*2;
            __nv_bfloat162 ph; ph.x = h0; ph.y = h1;
            __nv_bfloat162 pl; pl.x = l0; pl.y = l1;
            *(__nv_bfloat162*)&g_vh[off] = ph;
            *(__nv_bfloat162*)&g_vl[off] = pl;
        }
    } else {
        // ---- gate block (fp32) ----
        #pragma unroll
        for (int i = 0; i < 8; i++) {
            int row = m0 + ty*8 + i;
            #pragma unroll
            for (int j = 0; j < 4; j++) {
                int jg = n0 - D_DIM + tx*4 + j;
                float t = acc[i][j] + b_g[jg];
                g_g[(size_t)row*D_DIM + jg] = 1.0f / (1.0f + expf(-t));
            }
        }
    }
}

// ============================================================
// Kernel 5: attention GEMM via mma.sync bf16 (3-term split)
//   per CTA: M=128(q) x N=128(n) x K=384; cp.async double-buffered
//   smem stage: Ahi|Alo|Bhi|Blo 16KB each, XOR-swizzled rows of 128B
// ============================================================
__global__ __launch_bounds__(256, 1) void k_gemm_att_mma()
{
    extern __shared__ __align__(128) char smem[];
    const uint32_t STAGE = 65536;
    int tid = threadIdx.x;
    int nt = blockIdx.x, qt = blockIdx.y, h = blockIdx.z;
    int wid = tid >> 5, lane = tid & 31;
    int warpM = wid >> 2, warpN = wid & 3;
    uint32_t sbase = smem_u32(smem);

    const char* aHi = (const char*)(g_wh + (size_t)(h*3   + qt) * NKC * 8192);
    const char* aLo = (const char*)(g_wl + (size_t)(h*3   + qt) * NKC * 8192);
    const char* bHi = (const char*)(g_vh + (size_t)(h*128 + nt) * NKC * 8192);
    const char* bLo = (const char*)(g_vl + (size_t)(h*128 + nt) * NKC * 8192);

    float acc[4][4][4] = {};

    // ---- loader: one k-chunk (64 k) = 4 tiles x 16KB ----
    auto load_chunk = [&](int kc, int stage){
        size_t cb = (size_t)kc * 16384;
        #pragma unroll
        for (int t = 0; t < 16; t++) {
            int tile = t >> 2;                       // constant per t
            int c    = (t & 3) * 256 + tid;          // 16B chunk id in tile
            uint32_t x = (uint32_t)c * 16;
            uint32_t dst = sbase + stage*STAGE + (uint32_t)tile*16384
                         + (x ^ ((x >> 3) & 0x70));
            const char* src = (tile == 0 ? aHi : tile == 1 ? aLo : tile == 2 ? bHi : bLo)
                            + cb + x;
            cpasync16(dst, src);
        }
        asm volatile("cp.async.commit_group;" ::: "memory");
    };

    load_chunk(0, 0);
    for (int kc = 0; kc < NKC; kc++) {
        int stage = kc & 1;
        if (kc < NKC-1) load_chunk(kc+1, stage ^ 1);
        if (kc < NKC-1) asm volatile("cp.async.wait_group 1;" ::: "memory");
        else            asm volatile("cp.async.wait_group 0;" ::: "memory");
        __syncthreads();

        uint32_t sA_hi = sbase + stage*STAGE;
        uint32_t sA_lo = sA_hi + 16384;
        uint32_t sB_hi = sA_hi + 32768;
        uint32_t sB_lo = sA_hi + 49152;

        #pragma unroll
        for (int kt = 0; kt < 4; kt++) {
            uint32_t a_hi[4][4], a_lo[4][4], b_hi[4][2], b_lo[4][2];
            #pragma unroll
            for (int mt = 0; mt < 4; mt++) {
                int row = warpM*64 + mt*16 + (lane & 15);
                uint32_t x = (uint32_t)row*128 + kt*32 + ((lane >> 4)*16);
                uint32_t sw = x ^ ((x >> 3) & 0x70);
                LDSM_X4(a_hi[mt][0], a_hi[mt][1], a_hi[mt][2], a_hi[mt][3], sA_hi + sw);
                LDSM_X4(a_lo[mt][0], a_lo[mt][1], a_lo[mt][2], a_lo[mt][3], sA_lo + sw);
            }
            #pragma unroll
            for (int p = 0; p < 2; p++) {
                int g = lane >> 3;
                int ntile = p*2 + (g >> 1);
                int row = warpN*32 + ntile*8 + (lane & 7);
                uint32_t x = (uint32_t)row*128 + kt*32 + (g & 1)*16;
                uint32_t sw = x ^ ((x >> 3) & 0x70);
                uint32_t r[4];
                LDSM_X4(r[0], r[1], r[2], r[3], sB_hi + sw);
                b_hi[p*2][0] = r[0]; b_hi[p*2][1] = r[1];
                b_hi[p*2+1][0] = r[2]; b_hi[p*2+1][1] = r[3];
                LDSM_X4(r[0], r[1], r[2], r[3], sB_lo + sw);
                b_lo[p*2][0] = r[0]; b_lo[p*2][1] = r[1];
                b_lo[p*2+1][0] = r[2]; b_lo[p*2+1][1] = r[3];
            }
            // 3-term: hi*hi, hi*lo, lo*hi
            #pragma unroll
            for (int mt = 0; mt < 4; mt++)
                #pragma unroll
                for (int nn = 0; nn < 4; nn++)
                    mma_bf16(acc[mt][nn], a_hi[mt], b_hi[nn]);
            #pragma unroll
            for (int mt = 0; mt < 4; mt++)
                #pragma unroll
                for (int nn = 0; nn < 4; nn++)
                    mma_bf16(acc[mt][nn], a_hi[mt], b_lo[nn]);
            #pragma unroll
            for (int mt = 0; mt < 4; mt++)
                #pragma unroll
                for (int nn = 0; nn < 4; nn++)
                    mma_bf16(acc[mt][nn], a_lo[mt], b_hi[nn]);
        }
        __syncthreads();
    }

    // ---- epilogue: fp32 stores into g_o[(s*384+q)*256 + h*32 + c] ----
    #pragma unroll
    for (int mt = 0; mt < 4; mt++) {
        int q = qt*128 + warpM*64 + mt*16 + (lane >> 2);
        #pragma unroll
        for (int nn = 0; nn < 4; nn++) {
            int n = nt*128 + warpN*32 + nn*8 + (lane & 3)*2;
            int s = n >> 5, c = n & 31;
            size_t b0 = ((size_t)s*N_DIM + q    )*D_DIM + h*C_DIM + c;
            size_t b1 = ((size_t)s*N_DIM + q + 8)*D_DIM + h*C_DIM + c;
            *(float2*)&g_o[b0] = make_float2(acc[mt][nn][0], acc[mt][nn][1]);
            *(float2*)&g_o[b1] = make_float2(acc[mt][nn][2], acc[mt][nn][3]);
        }
    }
}

// ============================================================
// Kernel 6: GEMM (o*g)[196608,256] @ w_o[256,64] + b_o -> out
//   fp32 o,g; gating fused into A-tile load (round-2 proven)
// ============================================================
__global__ __launch_bounds__(256) void k_gemm_out(const float* __restrict__ w_o,
                                                  const float* __restrict__ b_o,
                                                  float* __restrict__ out)
{
    const int BM = 128, BN = 64, BK = 16;
    __shared__ __align__(16) float As[BK][BM];
    __shared__ __align__(16) float Bs[BK][BN];
    int tid = threadIdx.x;
    int tx  = tid & 15, ty = tid >> 4;
    int m0  = blockIdx.y * BM;
    int ar  = tid >> 2, ac = (tid & 3) * 4;
    int br  = tid >> 4, bc = (tid & 15) * 4;
    float acc[8][4] = {};

    for (int k0 = 0; k0 < D_DIM; k0 += BK) {
        #pragma unroll
        for (int half = 0; half < BM; half += 64) {
            size_t base = (size_t)(m0+ar+half)*D_DIM + k0 + ac;
            float4 ao = *(const float4*)(g_o + base);
            float4 ag = *(const float4*)(g_g + base);
            As[ac+0][ar+half] = ao.x*ag.x; As[ac+1][ar+half] = ao.y*ag.y;
            As[ac+2][ar+half] = ao.z*ag.z; As[ac+3][ar+half] = ao.w*ag.w;
        }
        float4 bv = *(const float4*)(w_o + (k0+br)*BN + bc);
        *(float4*)&Bs[br][bc] = bv;
        __syncthreads();
        #pragma unroll
        for (int kk = 0; kk < BK; kk++) {
            float rA[8], rB[4];
            #pragma unroll
            for (int i = 0; i < 8; i++) rA[i] = As[kk][ty*8+i];
            #pragma unroll
            for (int j = 0; j < 4; j++) rB[j] = Bs[kk][tx*4+j];
            #pragma unroll
            for (int i = 0; i < 8; i++)
                #pragma unroll
                for (int j = 0; j < 4; j++)
                    acc[i][j] += rA[i] * rB[j];
        }
        __syncthreads();
    }

    #pragma unroll
    for (int i = 0; i < 8; i++) {
        int row = m0 + ty*8 + i;
        #pragma unroll
        for (int j = 0; j < 4; j++) {
            int col = tx*4 + j;
            out[(size_t)row*CIN + col] = acc[i][j] + b_o[col];
        }
    }
}

// ============================================================
extern "C" void kernel_launch(void* const* d_in, const int* in_sizes, int n_in,
                              void* d_out, int out_size)
{
    const float* m       = (const float*)d_in[0];
    const float* z       = (const float*)d_in[1];
    const float* mask    = (const float*)d_in[2];
    const float* gamma_m = (const float*)d_in[3];
    const float* beta_m  = (const float*)d_in[4];
    const float* gamma_z = (const float*)d_in[5];
    const float* beta_z  = (const float*)d_in[6];
    const float* w_z     = (const float*)d_in[7];
    const float* b_z     = (const float*)d_in[8];
    const float* w_v     = (const float*)d_in[9];
    const float* b_v     = (const float*)d_in[10];
    const float* w_g     = (const float*)d_in[11];
    const float* b_g     = (const float*)d_in[12];
    const float* w_o     = (const float*)d_in[13];
    const float* b_o     = (const float*)d_in[14];
    float* out = (float*)d_out;

    cudaFuncSetAttribute(k_gemm_att_mma, cudaFuncAttributeMaxDynamicSharedMemorySize, 131072);

    k_lnz_logits<<<(N_DIM*N_DIM)/8, 256>>>(z, mask, gamma_z, beta_z, w_z, b_z);
    k_softmax<<<H_DIM*N_DIM, 128>>>();
    k_lnm<<<MROWS/8, 256>>>(m, gamma_m, beta_m);
    k_gemm_vg<<<dim3(8, MROWS/128), 256>>>(w_v, b_v, w_g, b_g);
    k_gemm_att_mma<<<dim3(128, 3, 8), 256, 131072>>>();
    k_gemm_out<<<dim3(1, MROWS/128), 256>>>(w_o, b_o, out);
}

// round 10
// speedup vs baseline: 1.9420x; 1.2795x over previous
#include <cuda_runtime.h>
#include <cuda_bf16.h>
#include <cuda_fp16.h>
#include <math.h>
#include <stdint.h>

#define S_DIM 512
#define N_DIM 384
#define CIN   64
#define CZ    128
#define H_DIM 8
#define C_DIM 32
#define D_DIM 256
#define INF_  1e9f
#define EPS_  1e-5f
#define MROWS (S_DIM*N_DIM)   // 196608
#define NKC   6               // K chunks of 64 covering K=384

// ---- scratch (static device arrays: no allocations allowed) ----
__device__ float g_w [(size_t)H_DIM*N_DIM*N_DIM];   // logits [h][q][k]
__device__ __half g_g [(size_t)MROWS*D_DIM];        // gate (fp16)
__device__ __half g_o [(size_t)MROWS*D_DIM];        // attention output (fp16)
// LN(m) split-bf16, k-major rows of 64 (128B rows)
__device__ __align__(1024) __nv_bfloat16 g_mnh[(size_t)MROWS*CIN];
__device__ __align__(1024) __nv_bfloat16 g_mnl[(size_t)MROWS*CIN];
// transposed [n=512][k=64] split-bf16 weights (w_v | w_g)
__device__ __align__(1024) __nv_bfloat16 g_wth[512*64];
__device__ __align__(1024) __nv_bfloat16 g_wtl[512*64];
// split-bf16 k-major staging tiles, 128 rows x 64 k each (8192 elems, 16KB)
// w: [h][qt(3)][kc(6)]   v: [h][nt(128)][kc(6)]
__device__ __align__(1024) __nv_bfloat16 g_wh[(size_t)H_DIM*3*NKC*8192];
__device__ __align__(1024) __nv_bfloat16 g_wl[(size_t)H_DIM*3*NKC*8192];
__device__ __align__(1024) __nv_bfloat16 g_vh[(size_t)H_DIM*128*NKC*8192];
__device__ __align__(1024) __nv_bfloat16 g_vl[(size_t)H_DIM*128*NKC*8192];

// ============================================================
// helpers (Ampere-class ISA only: valid on base sm_103 target)
// ============================================================
__device__ __forceinline__ uint32_t smem_u32(const void* p){
    uint32_t a;
    asm("{ .reg .u64 t; cvta.to.shared.u64 t, %1; cvt.u32.u64 %0, t; }" : "=r"(a) : "l"(p));
    return a;
}
#define LDSM_X4(r0,r1,r2,r3,addr) \
    asm volatile("ldmatrix.sync.aligned.m8n8.x4.shared.b16 {%0,%1,%2,%3}, [%4];" \
        : "=r"(r0),"=r"(r1),"=r"(r2),"=r"(r3) : "r"(addr))
__device__ __forceinline__ void mma_bf16(float* c, const uint32_t* a, const uint32_t* b){
    asm volatile("mma.sync.aligned.m16n8k16.row.col.f32.bf16.bf16.f32 "
        "{%0,%1,%2,%3}, {%4,%5,%6,%7}, {%8,%9}, {%0,%1,%2,%3};"
        : "+f"(c[0]),"+f"(c[1]),"+f"(c[2]),"+f"(c[3])
        : "r"(a[0]),"r"(a[1]),"r"(a[2]),"r"(a[3]), "r"(b[0]),"r"(b[1]));
}
__device__ __forceinline__ void cpasync16(uint32_t dst, const void* src){
    asm volatile("cp.async.cg.shared.global [%0], [%1], 16;" :: "r"(dst), "l"(src));
}

// ============================================================
// Kernel 0: transpose+split weights -> g_wth/g_wtl [n=512][k=64]
// ============================================================
__global__ void k_prep_w(const float* __restrict__ w_v, const float* __restrict__ w_g)
{
    int n = blockIdx.x, k = threadIdx.x;   // 512 blocks x 64 threads
    float val = (n < D_DIM) ? w_v[k*D_DIM + n] : w_g[k*D_DIM + (n - D_DIM)];
    __nv_bfloat16 hi = __float2bfloat16(val);
    __nv_bfloat16 lo = __float2bfloat16(val - __bfloat162float(hi));
    g_wth[n*64 + k] = hi;
    g_wtl[n*64 + k] = lo;
}

// ============================================================
// Kernel 1: LN(z) + logits (warp per (q,k) row)
// ============================================================
__global__ void k_lnz_logits(const float* __restrict__ z, const float* __restrict__ mask,
                             const float* __restrict__ gamma_z, const float* __restrict__ beta_z,
                             const float* __restrict__ w_z, const float* __restrict__ b_z)
{
    int gw   = (blockIdx.x * blockDim.x + threadIdx.x) >> 5;
    int lane = threadIdx.x & 31;
    if (gw >= N_DIM * N_DIM) return;
    int q = gw / N_DIM, k = gw % N_DIM;
    const float* zp = z + (size_t)gw * CZ;

    float x0 = zp[lane], x1 = zp[lane+32], x2 = zp[lane+64], x3 = zp[lane+96];
    float s  = x0+x1+x2+x3;
    float s2 = x0*x0 + x1*x1 + x2*x2 + x3*x3;
    #pragma unroll
    for (int o = 16; o; o >>= 1) {
        s  += __shfl_xor_sync(0xffffffffu, s,  o);
        s2 += __shfl_xor_sync(0xffffffffu, s2, o);
    }
    float mu  = s * (1.0f / CZ);
    float inv = rsqrtf(s2 * (1.0f / CZ) - mu*mu + EPS_);
    float n0 = (x0-mu)*inv*gamma_z[lane]    + beta_z[lane];
    float n1 = (x1-mu)*inv*gamma_z[lane+32] + beta_z[lane+32];
    float n2 = (x2-mu)*inv*gamma_z[lane+64] + beta_z[lane+64];
    float n3 = (x3-mu)*inv*gamma_z[lane+96] + beta_z[lane+96];

    float acc[H_DIM];
    #pragma unroll
    for (int h = 0; h < H_DIM; h++) {
        acc[h] = n0 * w_z[lane*H_DIM + h]
               + n1 * w_z[(lane+32)*H_DIM + h]
               + n2 * w_z[(lane+64)*H_DIM + h]
               + n3 * w_z[(lane+96)*H_DIM + h];
        #pragma unroll
        for (int o = 16; o; o >>= 1)
            acc[h] += __shfl_xor_sync(0xffffffffu, acc[h], o);
    }
    if (lane == 0) {
        float bias = INF_ * (mask[gw] - 1.0f);
        #pragma unroll
        for (int h = 0; h < H_DIM; h++)
            g_w[((size_t)h*N_DIM + q)*N_DIM + k] = acc[h] + b_z[h] + bias;
    }
}

// ============================================================
// Kernel 2: softmax per (h,q) row -> split-bf16 staging (k-major)
// ============================================================
__global__ void k_softmax()
{
    int row = blockIdx.x;                   // h*384 + q
    int h = row / N_DIM, q = row - h*N_DIM;
    const float* p = g_w + (size_t)row * N_DIM;
    int tid = threadIdx.x;                  // 128 threads, 3 elems each
    __shared__ float red[128];

    float v0 = p[tid], v1 = p[tid+128], v2 = p[tid+256];
    float mx = fmaxf(v0, fmaxf(v1, v2));
    red[tid] = mx; __syncthreads();
    for (int o = 64; o; o >>= 1) { if (tid < o) red[tid] = fmaxf(red[tid], red[tid+o]); __syncthreads(); }
    mx = red[0]; __syncthreads();

    float e0 = expf(v0-mx), e1 = expf(v1-mx), e2 = expf(v2-mx);
    red[tid] = e0 + e1 + e2; __syncthreads();
    for (int o = 64; o; o >>= 1) { if (tid < o) red[tid] += red[tid+o]; __syncthreads(); }
    float inv = 1.0f / red[0];

    int r = q & 127;
    size_t blkbase = (size_t)((h*3 + (q >> 7)) * NKC);
    float ev[3] = {e0, e1, e2};
    #pragma unroll
    for (int t = 0; t < 3; t++) {
        int k = tid + t*128;
        float wv = ev[t] * inv;
        __nv_bfloat16 hi = __float2bfloat16(wv);
        __nv_bfloat16 lo = __float2bfloat16(wv - __bfloat162float(hi));
        int kc = k >> 6, kk = k & 63;
        size_t off = (blkbase + kc) * 8192 + (size_t)(r*64 + kk);
        g_wh[off] = hi;
        g_wl[off] = lo;
    }
}

// ============================================================
// Kernel 3: LN(m) -> split-bf16 mn (k-major rows of 64)
// ============================================================
__global__ void k_lnm(const float* __restrict__ m,
                      const float* __restrict__ gamma_m, const float* __restrict__ beta_m)
{
    int gw   = (blockIdx.x * blockDim.x + threadIdx.x) >> 5;
    int lane = threadIdx.x & 31;
    if (gw >= MROWS) return;
    const float* mp = m + (size_t)gw * CIN;
    float a = mp[lane], b = mp[lane+32];
    float s = a + b, s2 = a*a + b*b;
    #pragma unroll
    for (int o = 16; o; o >>= 1) {
        s  += __shfl_xor_sync(0xffffffffu, s,  o);
        s2 += __shfl_xor_sync(0xffffffffu, s2, o);
    }
    float mu  = s * (1.0f / CIN);
    float inv = rsqrtf(s2 * (1.0f / CIN) - mu*mu + EPS_);
    float na = (a-mu)*inv*gamma_m[lane]    + beta_m[lane];
    float nb = (b-mu)*inv*gamma_m[lane+32] + beta_m[lane+32];
    __nv_bfloat16 ha = __float2bfloat16(na);
    __nv_bfloat16 hb = __float2bfloat16(nb);
    size_t base = (size_t)gw * CIN;
    g_mnh[base + lane]      = ha;
    g_mnh[base + lane + 32] = hb;
    g_mnl[base + lane]      = __float2bfloat16(na - __bfloat162float(ha));
    g_mnl[base + lane + 32] = __float2bfloat16(nb - __bfloat162float(hb));
}

// ============================================================
// Kernel 4: v/gate projection via mma.sync bf16 (3-term split)
//   per CTA: M=128(rows of mn) x N=128(cols of [w_v|w_g]) x K=64
//   n0 in {0,128}: v -> T-transpose -> split-bf16 staging
//   n0 in {256,384}: gate -> sigmoid -> g_g (fp16)
// ============================================================
__global__ __launch_bounds__(256, 1) void k_gemm_vg_mma(const float* __restrict__ b_v,
                                                        const float* __restrict__ b_g)
{
    extern __shared__ __align__(128) char smem[];
    int tid = threadIdx.x;
    int n0 = blockIdx.x * 128;
    int m0 = blockIdx.y * 128;
    int wid = tid >> 5, lane = tid & 31;
    int warpM = wid >> 2, warpN = wid & 3;
    uint32_t sbase = smem_u32(smem);

    const char* aHi = (const char*)(g_mnh + (size_t)m0*64);
    const char* aLo = (const char*)(g_mnl + (size_t)m0*64);
    const char* bHi = (const char*)(g_wth + (size_t)n0*64);
    const char* bLo = (const char*)(g_wtl + (size_t)n0*64);

    // ---- load 4 tiles x 16KB (swizzled) ----
    #pragma unroll
    for (int t = 0; t < 16; t++) {
        int tile = t >> 2;
        int c    = (t & 3) * 256 + tid;
        uint32_t x = (uint32_t)c * 16;
        uint32_t dst = sbase + (uint32_t)tile*16384 + (x ^ ((x >> 3) & 0x70));
        const char* src = (tile == 0 ? aHi : tile == 1 ? aLo : tile == 2 ? bHi : bLo) + x;
        cpasync16(dst, src);
    }
    asm volatile("cp.async.commit_group;" ::: "memory");
    asm volatile("cp.async.wait_group 0;" ::: "memory");
    __syncthreads();

    uint32_t sA_hi = sbase;
    uint32_t sA_lo = sbase + 16384;
    uint32_t sB_hi = sbase + 32768;
    uint32_t sB_lo = sbase + 49152;

    float acc[4][4][4] = {};
    #pragma unroll
    for (int kt = 0; kt < 4; kt++) {
        uint32_t a_hi[4][4], a_lo[4][4], b_hi[4][2], b_lo[4][2];
        #pragma unroll
        for (int mt = 0; mt < 4; mt++) {
            int row = warpM*64 + mt*16 + (lane & 15);
            uint32_t x = (uint32_t)row*128 + kt*32 + ((lane >> 4)*16);
            uint32_t sw = x ^ ((x >> 3) & 0x70);
            LDSM_X4(a_hi[mt][0], a_hi[mt][1], a_hi[mt][2], a_hi[mt][3], sA_hi + sw);
            LDSM_X4(a_lo[mt][0], a_lo[mt][1], a_lo[mt][2], a_lo[mt][3], sA_lo + sw);
        }
        #pragma unroll
        for (int p = 0; p < 2; p++) {
            int g = lane >> 3;
            int ntile = p*2 + (g >> 1);
            int row = warpN*32 + ntile*8 + (lane & 7);
            uint32_t x = (uint32_t)row*128 + kt*32 + (g & 1)*16;
            uint32_t sw = x ^ ((x >> 3) & 0x70);
            uint32_t r[4];
            LDSM_X4(r[0], r[1], r[2], r[3], sB_hi + sw);
            b_hi[p*2][0] = r[0]; b_hi[p*2][1] = r[1];
            b_hi[p*2+1][0] = r[2]; b_hi[p*2+1][1] = r[3];
            LDSM_X4(r[0], r[1], r[2], r[3], sB_lo + sw);
            b_lo[p*2][0] = r[0]; b_lo[p*2][1] = r[1];
            b_lo[p*2+1][0] = r[2]; b_lo[p*2+1][1] = r[3];
        }
        #pragma unroll
        for (int mt = 0; mt < 4; mt++)
            #pragma unroll
            for (int nn = 0; nn < 4; nn++)
                mma_bf16(acc[mt][nn], a_hi[mt], b_hi[nn]);
        #pragma unroll
        for (int mt = 0; mt < 4; mt++)
            #pragma unroll
            for (int nn = 0; nn < 4; nn++)
                mma_bf16(acc[mt][nn], a_hi[mt], b_lo[nn]);
        #pragma unroll
        for (int mt = 0; mt < 4; mt++)
            #pragma unroll
            for (int nn = 0; nn < 4; nn++)
                mma_bf16(acc[mt][nn], a_lo[mt], b_hi[nn]);
    }
    __syncthreads();

    if (n0 < D_DIM) {
        // ---- v: transpose fragments into T[col][row], then stage split-bf16 ----
        float* T = (float*)smem;   // 128 x 129
        #pragma unroll
        for (int mt = 0; mt < 4; mt++) {
            int qr = warpM*64 + mt*16 + (lane >> 2);
            #pragma unroll
            for (int nn = 0; nn < 4; nn++) {
                int nc = warpN*32 + nn*8 + (lane & 3)*2;
                float bv0 = b_v[n0 + nc], bv1 = b_v[n0 + nc + 1];
                T[(nc  )*129 + qr    ] = acc[mt][nn][0] + bv0;
                T[(nc+1)*129 + qr    ] = acc[mt][nn][1] + bv1;
                T[(nc  )*129 + qr + 8] = acc[mt][nn][2] + bv0;
                T[(nc+1)*129 + qr + 8] = acc[mt][nn][3] + bv1;
            }
        }
        __syncthreads();

        int sI = m0 / N_DIM;           // 128-row blocks never straddle s
        int kb = m0 - sI * N_DIM;      // 0,128,256
        int nt = sI >> 2;
        int j   = tid >> 1, kcl = tid & 1;
        int col = n0 + j;
        int h   = col >> 5, c = col & 31;
        int nr  = ((sI & 3) << 5) + c;
        int kc  = (kb >> 6) + kcl;
        size_t blk = ((size_t)(h*128 + nt)*NKC + kc) * 8192;
        const float* Tr = T + j*129 + kcl*64;
        #pragma unroll
        for (int kk = 0; kk < 64; kk += 2) {
            float f0 = Tr[kk], f1 = Tr[kk+1];
            __nv_bfloat16 h0 = __float2bfloat16(f0);
            __nv_bfloat16 h1 = __float2bfloat16(f1);
            __nv_bfloat162 ph; ph.x = h0; ph.y = h1;
            __nv_bfloat162 pl;
            pl.x = __float2bfloat16(f0 - __bfloat162float(h0));
            pl.y = __float2bfloat16(f1 - __bfloat162float(h1));
            *(__nv_bfloat162*)&g_vh[blk + (size_t)nr*64 + kk] = ph;
            *(__nv_bfloat162*)&g_vl[blk + (size_t)nr*64 + kk] = pl;
        }
    } else {
        // ---- gate: sigmoid -> fp16 ----
        int jb = n0 - D_DIM;
        #pragma unroll
        for (int mt = 0; mt < 4; mt++) {
            int row = m0 + warpM*64 + mt*16 + (lane >> 2);
            #pragma unroll
            for (int nn = 0; nn < 4; nn++) {
                int jg = jb + warpN*32 + nn*8 + (lane & 3)*2;
                float bg0 = b_g[jg], bg1 = b_g[jg+1];
                float t0 = acc[mt][nn][0] + bg0, t1 = acc[mt][nn][1] + bg1;
                float t2 = acc[mt][nn][2] + bg0, t3 = acc[mt][nn][3] + bg1;
                *(__half2*)&g_g[(size_t)row*D_DIM + jg] =
                    __floats2half2_rn(1.0f/(1.0f+expf(-t0)), 1.0f/(1.0f+expf(-t1)));
                *(__half2*)&g_g[(size_t)(row+8)*D_DIM + jg] =
                    __floats2half2_rn(1.0f/(1.0f+expf(-t2)), 1.0f/(1.0f+expf(-t3)));
            }
        }
    }
}

// ============================================================
// Kernel 5: attention GEMM via mma.sync bf16 (3-term split)
//   per CTA: M=128(q) x N=128(n) x K=384; cp.async double-buffered
// ============================================================
__global__ __launch_bounds__(256, 1) void k_gemm_att_mma()
{
    extern __shared__ __align__(128) char smem[];
    const uint32_t STAGE = 65536;
    int tid = threadIdx.x;
    int nt = blockIdx.x, qt = blockIdx.y, h = blockIdx.z;
    int wid = tid >> 5, lane = tid & 31;
    int warpM = wid >> 2, warpN = wid & 3;
    uint32_t sbase = smem_u32(smem);

    const char* aHi = (const char*)(g_wh + (size_t)(h*3   + qt) * NKC * 8192);
    const char* aLo = (const char*)(g_wl + (size_t)(h*3   + qt) * NKC * 8192);
    const char* bHi = (const char*)(g_vh + (size_t)(h*128 + nt) * NKC * 8192);
    const char* bLo = (const char*)(g_vl + (size_t)(h*128 + nt) * NKC * 8192);

    float acc[4][4][4] = {};

    auto load_chunk = [&](int kc, int stage){
        size_t cb = (size_t)kc * 16384;
        #pragma unroll
        for (int t = 0; t < 16; t++) {
            int tile = t >> 2;
            int c    = (t & 3) * 256 + tid;
            uint32_t x = (uint32_t)c * 16;
            uint32_t dst = sbase + stage*STAGE + (uint32_t)tile*16384
                         + (x ^ ((x >> 3) & 0x70));
            const char* src = (tile == 0 ? aHi : tile == 1 ? aLo : tile == 2 ? bHi : bLo)
                            + cb + x;
            cpasync16(dst, src);
        }
        asm volatile("cp.async.commit_group;" ::: "memory");
    };

    load_chunk(0, 0);
    for (int kc = 0; kc < NKC; kc++) {
        int stage = kc & 1;
        if (kc < NKC-1) load_chunk(kc+1, stage ^ 1);
        if (kc < NKC-1) asm volatile("cp.async.wait_group 1;" ::: "memory");
        else            asm volatile("cp.async.wait_group 0;" ::: "memory");
        __syncthreads();

        uint32_t sA_hi = sbase + stage*STAGE;
        uint32_t sA_lo = sA_hi + 16384;
        uint32_t sB_hi = sA_hi + 32768;
        uint32_t sB_lo = sA_hi + 49152;

        #pragma unroll
        for (int kt = 0; kt < 4; kt++) {
            uint32_t a_hi[4][4], a_lo[4][4], b_hi[4][2], b_lo[4][2];
            #pragma unroll
            for (int mt = 0; mt < 4; mt++) {
                int row = warpM*64 + mt*16 + (lane & 15);
                uint32_t x = (uint32_t)row*128 + kt*32 + ((lane >> 4)*16);
                uint32_t sw = x ^ ((x >> 3) & 0x70);
                LDSM_X4(a_hi[mt][0], a_hi[mt][1], a_hi[mt][2], a_hi[mt][3], sA_hi + sw);
                LDSM_X4(a_lo[mt][0], a_lo[mt][1], a_lo[mt][2], a_lo[mt][3], sA_lo + sw);
            }
            #pragma unroll
            for (int p = 0; p < 2; p++) {
                int g = lane >> 3;
                int ntile = p*2 + (g >> 1);
                int row = warpN*32 + ntile*8 + (lane & 7);
                uint32_t x = (uint32_t)row*128 + kt*32 + (g & 1)*16;
                uint32_t sw = x ^ ((x >> 3) & 0x70);
                uint32_t r[4];
                LDSM_X4(r[0], r[1], r[2], r[3], sB_hi + sw);
                b_hi[p*2][0] = r[0]; b_hi[p*2][1] = r[1];
                b_hi[p*2+1][0] = r[2]; b_hi[p*2+1][1] = r[3];
                LDSM_X4(r[0], r[1], r[2], r[3], sB_lo + sw);
                b_lo[p*2][0] = r[0]; b_lo[p*2][1] = r[1];
                b_lo[p*2+1][0] = r[2]; b_lo[p*2+1][1] = r[3];
            }
            #pragma unroll
            for (int mt = 0; mt < 4; mt++)
                #pragma unroll
                for (int nn = 0; nn < 4; nn++)
                    mma_bf16(acc[mt][nn], a_hi[mt], b_hi[nn]);
            #pragma unroll
            for (int mt = 0; mt < 4; mt++)
                #pragma unroll
                for (int nn = 0; nn < 4; nn++)
                    mma_bf16(acc[mt][nn], a_hi[mt], b_lo[nn]);
            #pragma unroll
            for (int mt = 0; mt < 4; mt++)
                #pragma unroll
                for (int nn = 0; nn < 4; nn++)
                    mma_bf16(acc[mt][nn], a_lo[mt], b_hi[nn]);
        }
        __syncthreads();
    }

    // ---- epilogue: fp16 stores into g_o[(s*384+q)*256 + h*32 + c] ----
    #pragma unroll
    for (int mt = 0; mt < 4; mt++) {
        int q = qt*128 + warpM*64 + mt*16 + (lane >> 2);
        #pragma unroll
        for (int nn = 0; nn < 4; nn++) {
            int n = nt*128 + warpN*32 + nn*8 + (lane & 3)*2;
            int s = n >> 5, c = n & 31;
            size_t b0 = ((size_t)s*N_DIM + q    )*D_DIM + h*C_DIM + c;
            size_t b1 = ((size_t)s*N_DIM + q + 8)*D_DIM + h*C_DIM + c;
            *(__half2*)&g_o[b0] = __floats2half2_rn(acc[mt][nn][0], acc[mt][nn][1]);
            *(__half2*)&g_o[b1] = __floats2half2_rn(acc[mt][nn][2], acc[mt][nn][3]);
        }
    }
}

// ============================================================
// Kernel 6: GEMM (o*g)[196608,256] @ w_o[256,64] + b_o -> out
//   o,g fp16; BM=256, 8x8 microtile, 256 threads
// ============================================================
__global__ __launch_bounds__(256) void k_gemm_out(const float* __restrict__ w_o,
                                                  const float* __restrict__ b_o,
                                                  float* __restrict__ out)
{
    const int BM = 256, BN = 64, BK = 16;
    __shared__ __align__(16) float As[BK][BM];
    __shared__ __align__(16) float Bs[BK][BN];
    int tid = threadIdx.x;
    int tx  = tid & 7, ty = tid >> 3;     // 8 x 32
    int m0  = blockIdx.y * BM;
    int br  = tid >> 4, bc = (tid & 15) * 4;
    float acc[8][8] = {};

    for (int k0 = 0; k0 < D_DIM; k0 += BK) {
        size_t base = (size_t)(m0 + tid)*D_DIM + k0;
        uint4 ro0 = *(const uint4*)(g_o + base);
        uint4 ro1 = *(const uint4*)(g_o + base + 8);
        uint4 rg0 = *(const uint4*)(g_g + base);
        uint4 rg1 = *(const uint4*)(g_g + base + 8);
        const __half2* po0 = (const __half2*)&ro0;
        const __half2* po1 = (const __half2*)&ro1;
        const __half2* pg0 = (const __half2*)&rg0;
        const __half2* pg1 = (const __half2*)&rg1;
        #pragma unroll
        for (int u = 0; u < 4; u++) {
            float2 fo = __half22float2(po0[u]);
            float2 fg = __half22float2(pg0[u]);
            As[2*u    ][tid] = fo.x * fg.x;
            As[2*u + 1][tid] = fo.y * fg.y;
            fo = __half22float2(po1[u]);
            fg = __half22float2(pg1[u]);
            As[8 + 2*u    ][tid] = fo.x * fg.x;
            As[8 + 2*u + 1][tid] = fo.y * fg.y;
        }
        float4 bv = *(const float4*)(w_o + (k0+br)*BN + bc);
        *(float4*)&Bs[br][bc] = bv;
        __syncthreads();
        #pragma unroll
        for (int kk = 0; kk < BK; kk++) {
            float rA[8], rB[8];
            #pragma unroll
            for (int i = 0; i < 8; i++) rA[i] = As[kk][ty*8+i];
            #pragma unroll
            for (int j = 0; j < 8; j++) rB[j] = Bs[kk][tx*8+j];
            #pragma unroll
            for (int i = 0; i < 8; i++)
                #pragma unroll
                for (int j = 0; j < 8; j++)
                    acc[i][j] += rA[i] * rB[j];
        }
        __syncthreads();
    }

    #pragma unroll
    for (int i = 0; i < 8; i++) {
        int row = m0 + ty*8 + i;
        #pragma unroll
        for (int j = 0; j < 8; j += 4) {
            int col = tx*8 + j;
            float4 v4 = make_float4(acc[i][j]   + b_o[col],
                                    acc[i][j+1] + b_o[col+1],
                                    acc[i][j+2] + b_o[col+2],
                                    acc[i][j+3] + b_o[col+3]);
            *(float4*)(out + (size_t)row*CIN + col) = v4;
        }
    }
}

// ============================================================
extern "C" void kernel_launch(void* const* d_in, const int* in_sizes, int n_in,
                              void* d_out, int out_size)
{
    const float* m       = (const float*)d_in[0];
    const float* z       = (const float*)d_in[1];
    const float* mask    = (const float*)d_in[2];
    const float* gamma_m = (const float*)d_in[3];
    const float* beta_m  = (const float*)d_in[4];
    const float* gamma_z = (const float*)d_in[5];
    const float* beta_z  = (const float*)d_in[6];
    const float* w_z     = (const float*)d_in[7];
    const float* b_z     = (const float*)d_in[8];
    const float* w_v     = (const float*)d_in[9];
    const float* b_v     = (const float*)d_in[10];
    const float* w_g     = (const float*)d_in[11];
    const float* b_g     = (const float*)d_in[12];
    const float* w_o     = (const float*)d_in[13];
    const float* b_o     = (const float*)d_in[14];
    float* out = (float*)d_out;

    cudaFuncSetAttribute(k_gemm_att_mma, cudaFuncAttributeMaxDynamicSharedMemorySize, 131072);
    cudaFuncSetAttribute(k_gemm_vg_mma,  cudaFuncAttributeMaxDynamicSharedMemorySize, 66048);

    k_prep_w<<<512, 64>>>(w_v, w_g);
    k_lnz_logits<<<(N_DIM*N_DIM)/8, 256>>>(z, mask, gamma_z, beta_z, w_z, b_z);
    k_softmax<<<H_DIM*N_DIM, 128>>>();
    k_lnm<<<MROWS/8, 256>>>(m, gamma_m, beta_m);
    k_gemm_vg_mma<<<dim3(4, MROWS/128), 256, 66048>>>(b_v, b_g);
    k_gemm_att_mma<<<dim3(128, 3, 8), 256, 131072>>>();
    k_gemm_out<<<dim3(1, MROWS/256), 256>>>(w_o, b_o, out);
}

// round 11
// speedup vs baseline: 2.2520x; 1.1596x over previous
#include <cuda_runtime.h>
#include <cuda_bf16.h>
#include <cuda_fp16.h>
#include <math.h>
#include <stdint.h>

#define S_DIM 512
#define N_DIM 384
#define CIN   64
#define CZ    128
#define H_DIM 8
#define C_DIM 32
#define D_DIM 256
#define INF_  1e9f
#define EPS_  1e-5f
#define MROWS (S_DIM*N_DIM)   // 196608
#define NKC   6               // K chunks of 64 covering K=384

// ---- scratch (static device arrays: no allocations allowed) ----
__device__ float g_w [(size_t)H_DIM*N_DIM*N_DIM];   // logits [h][q][k]
__device__ __half g_g [(size_t)MROWS*D_DIM];        // gate (fp16)
__device__ __half g_o [(size_t)MROWS*D_DIM];        // attention output (fp16)
// LN(m) split-bf16, k-major rows of 64 (128B rows)
__device__ __align__(1024) __nv_bfloat16 g_mnh[(size_t)MROWS*CIN];
__device__ __align__(1024) __nv_bfloat16 g_mnl[(size_t)MROWS*CIN];
// transposed [n=512][k=64] split-bf16 weights (w_v | w_g)
__device__ __align__(1024) __nv_bfloat16 g_wth[512*64];
__device__ __align__(1024) __nv_bfloat16 g_wtl[512*64];
// transposed [n=64][k=256] split-fp16 w_o
__device__ __align__(1024) __half g_woth[64*256];
__device__ __align__(1024) __half g_wotl[64*256];
// split-bf16 k-major staging tiles, 128 rows x 64 k each (8192 elems, 16KB)
// w: [h][qt(3)][kc(6)]   v: [h][nt(128)][kc(6)]
__device__ __align__(1024) __nv_bfloat16 g_wh[(size_t)H_DIM*3*NKC*8192];
__device__ __align__(1024) __nv_bfloat16 g_wl[(size_t)H_DIM*3*NKC*8192];
__device__ __align__(1024) __nv_bfloat16 g_vh[(size_t)H_DIM*128*NKC*8192];
__device__ __align__(1024) __nv_bfloat16 g_vl[(size_t)H_DIM*128*NKC*8192];

// ============================================================
// helpers (Ampere-class ISA only: valid on base sm_103 target)
// ============================================================
__device__ __forceinline__ uint32_t smem_u32(const void* p){
    uint32_t a;
    asm("{ .reg .u64 t; cvta.to.shared.u64 t, %1; cvt.u32.u64 %0, t; }" : "=r"(a) : "l"(p));
    return a;
}
#define LDSM_X4(r0,r1,r2,r3,addr) \
    asm volatile("ldmatrix.sync.aligned.m8n8.x4.shared.b16 {%0,%1,%2,%3}, [%4];" \
        : "=r"(r0),"=r"(r1),"=r"(r2),"=r"(r3) : "r"(addr))
__device__ __forceinline__ void mma_bf16(float* c, const uint32_t* a, const uint32_t* b){
    asm volatile("mma.sync.aligned.m16n8k16.row.col.f32.bf16.bf16.f32 "
        "{%0,%1,%2,%3}, {%4,%5,%6,%7}, {%8,%9}, {%0,%1,%2,%3};"
        : "+f"(c[0]),"+f"(c[1]),"+f"(c[2]),"+f"(c[3])
        : "r"(a[0]),"r"(a[1]),"r"(a[2]),"r"(a[3]), "r"(b[0]),"r"(b[1]));
}
__device__ __forceinline__ void mma_fp16(float* c, const uint32_t* a, const uint32_t* b){
    asm volatile("mma.sync.aligned.m16n8k16.row.col.f32.f16.f16.f32 "
        "{%0,%1,%2,%3}, {%4,%5,%6,%7}, {%8,%9}, {%0,%1,%2,%3};"
        : "+f"(c[0]),"+f"(c[1]),"+f"(c[2]),"+f"(c[3])
        : "r"(a[0]),"r"(a[1]),"r"(a[2]),"r"(a[3]), "r"(b[0]),"r"(b[1]));
}
__device__ __forceinline__ void cpasync16(uint32_t dst, const void* src){
    asm volatile("cp.async.cg.shared.global [%0], [%1], 16;" :: "r"(dst), "l"(src));
}

// ============================================================
// Kernel 0a: transpose+split weights -> g_wth/g_wtl [n=512][k=64]
// ============================================================
__global__ void k_prep_w(const float* __restrict__ w_v, const float* __restrict__ w_g)
{
    int n = blockIdx.x, k = threadIdx.x;   // 512 blocks x 64 threads
    float val = (n < D_DIM) ? w_v[k*D_DIM + n] : w_g[k*D_DIM + (n - D_DIM)];
    __nv_bfloat16 hi = __float2bfloat16(val);
    __nv_bfloat16 lo = __float2bfloat16(val - __bfloat162float(hi));
    g_wth[n*64 + k] = hi;
    g_wtl[n*64 + k] = lo;
}

// ============================================================
// Kernel 0b: transpose+split w_o -> g_woth/g_wotl [n=64][k=256]
// ============================================================
__global__ void k_prep_wo(const float* __restrict__ w_o)
{
    int n = blockIdx.x, k = threadIdx.x;   // 64 blocks x 256 threads
    float val = w_o[k*CIN + n];
    __half hi = __float2half_rn(val);
    __half lo = __float2half_rn(val - __half2float(hi));
    g_woth[n*256 + k] = hi;
    g_wotl[n*256 + k] = lo;
}

// ============================================================
// Kernel 1: LN(z) + logits (warp per (q,k) row)
// ============================================================
__global__ void k_lnz_logits(const float* __restrict__ z, const float* __restrict__ mask,
                             const float* __restrict__ gamma_z, const float* __restrict__ beta_z,
                             const float* __restrict__ w_z, const float* __restrict__ b_z)
{
    int gw   = (blockIdx.x * blockDim.x + threadIdx.x) >> 5;
    int lane = threadIdx.x & 31;
    if (gw >= N_DIM * N_DIM) return;
    int q = gw / N_DIM, k = gw % N_DIM;
    const float* zp = z + (size_t)gw * CZ;

    float x0 = zp[lane], x1 = zp[lane+32], x2 = zp[lane+64], x3 = zp[lane+96];
    float s  = x0+x1+x2+x3;
    float s2 = x0*x0 + x1*x1 + x2*x2 + x3*x3;
    #pragma unroll
    for (int o = 16; o; o >>= 1) {
        s  += __shfl_xor_sync(0xffffffffu, s,  o);
        s2 += __shfl_xor_sync(0xffffffffu, s2, o);
    }
    float mu  = s * (1.0f / CZ);
    float inv = rsqrtf(s2 * (1.0f / CZ) - mu*mu + EPS_);
    float n0 = (x0-mu)*inv*gamma_z[lane]    + beta_z[lane];
    float n1 = (x1-mu)*inv*gamma_z[lane+32] + beta_z[lane+32];
    float n2 = (x2-mu)*inv*gamma_z[lane+64] + beta_z[lane+64];
    float n3 = (x3-mu)*inv*gamma_z[lane+96] + beta_z[lane+96];

    float acc[H_DIM];
    #pragma unroll
    for (int h = 0; h < H_DIM; h++) {
        acc[h] = n0 * w_z[lane*H_DIM + h]
               + n1 * w_z[(lane+32)*H_DIM + h]
               + n2 * w_z[(lane+64)*H_DIM + h]
               + n3 * w_z[(lane+96)*H_DIM + h];
        #pragma unroll
        for (int o = 16; o; o >>= 1)
            acc[h] += __shfl_xor_sync(0xffffffffu, acc[h], o);
    }
    if (lane == 0) {
        float bias = INF_ * (mask[gw] - 1.0f);
        #pragma unroll
        for (int h = 0; h < H_DIM; h++)
            g_w[((size_t)h*N_DIM + q)*N_DIM + k] = acc[h] + b_z[h] + bias;
    }
}

// ============================================================
// Kernel 2: softmax per (h,q) row -> split-bf16 staging (k-major)
// ============================================================
__global__ void k_softmax()
{
    int row = blockIdx.x;                   // h*384 + q
    int h = row / N_DIM, q = row - h*N_DIM;
    const float* p = g_w + (size_t)row * N_DIM;
    int tid = threadIdx.x;                  // 128 threads, 3 elems each
    __shared__ float red[128];

    float v0 = p[tid], v1 = p[tid+128], v2 = p[tid+256];
    float mx = fmaxf(v0, fmaxf(v1, v2));
    red[tid] = mx; __syncthreads();
    for (int o = 64; o; o >>= 1) { if (tid < o) red[tid] = fmaxf(red[tid], red[tid+o]); __syncthreads(); }
    mx = red[0]; __syncthreads();

    float e0 = expf(v0-mx), e1 = expf(v1-mx), e2 = expf(v2-mx);
    red[tid] = e0 + e1 + e2; __syncthreads();
    for (int o = 64; o; o >>= 1) { if (tid < o) red[tid] += red[tid+o]; __syncthreads(); }
    float inv = 1.0f / red[0];

    int r = q & 127;
    size_t blkbase = (size_t)((h*3 + (q >> 7)) * NKC);
    float ev[3] = {e0, e1, e2};
    #pragma unroll
    for (int t = 0; t < 3; t++) {
        int k = tid + t*128;
        float wv = ev[t] * inv;
        __nv_bfloat16 hi = __float2bfloat16(wv);
        __nv_bfloat16 lo = __float2bfloat16(wv - __bfloat162float(hi));
        int kc = k >> 6, kk = k & 63;
        size_t off = (blkbase + kc) * 8192 + (size_t)(r*64 + kk);
        g_wh[off] = hi;
        g_wl[off] = lo;
    }
}

// ============================================================
// Kernel 3: LN(m) -> split-bf16 mn (k-major rows of 64)
// ============================================================
__global__ void k_lnm(const float* __restrict__ m,
                      const float* __restrict__ gamma_m, const float* __restrict__ beta_m)
{
    int gw   = (blockIdx.x * blockDim.x + threadIdx.x) >> 5;
    int lane = threadIdx.x & 31;
    if (gw >= MROWS) return;
    const float* mp = m + (size_t)gw * CIN;
    float a = mp[lane], b = mp[lane+32];
    float s = a + b, s2 = a*a + b*b;
    #pragma unroll
    for (int o = 16; o; o >>= 1) {
        s  += __shfl_xor_sync(0xffffffffu, s,  o);
        s2 += __shfl_xor_sync(0xffffffffu, s2, o);
    }
    float mu  = s * (1.0f / CIN);
    float inv = rsqrtf(s2 * (1.0f / CIN) - mu*mu + EPS_);
    float na = (a-mu)*inv*gamma_m[lane]    + beta_m[lane];
    float nb = (b-mu)*inv*gamma_m[lane+32] + beta_m[lane+32];
    __nv_bfloat16 ha = __float2bfloat16(na);
    __nv_bfloat16 hb = __float2bfloat16(nb);
    size_t base = (size_t)gw * CIN;
    g_mnh[base + lane]      = ha;
    g_mnh[base + lane + 32] = hb;
    g_mnl[base + lane]      = __float2bfloat16(na - __bfloat162float(ha));
    g_mnl[base + lane + 32] = __float2bfloat16(nb - __bfloat162float(hb));
}

// ============================================================
// Kernel 4: v/gate projection via mma.sync bf16 (3-term split)
// ============================================================
__global__ __launch_bounds__(256, 1) void k_gemm_vg_mma(const float* __restrict__ b_v,
                                                        const float* __restrict__ b_g)
{
    extern __shared__ __align__(128) char smem[];
    int tid = threadIdx.x;
    int n0 = blockIdx.x * 128;
    int m0 = blockIdx.y * 128;
    int wid = tid >> 5, lane = tid & 31;
    int warpM = wid >> 2, warpN = wid & 3;
    uint32_t sbase = smem_u32(smem);

    const char* aHi = (const char*)(g_mnh + (size_t)m0*64);
    const char* aLo = (const char*)(g_mnl + (size_t)m0*64);
    const char* bHi = (const char*)(g_wth + (size_t)n0*64);
    const char* bLo = (const char*)(g_wtl + (size_t)n0*64);

    #pragma unroll
    for (int t = 0; t < 16; t++) {
        int tile = t >> 2;
        int c    = (t & 3) * 256 + tid;
        uint32_t x = (uint32_t)c * 16;
        uint32_t dst = sbase + (uint32_t)tile*16384 + (x ^ ((x >> 3) & 0x70));
        const char* src = (tile == 0 ? aHi : tile == 1 ? aLo : tile == 2 ? bHi : bLo) + x;
        cpasync16(dst, src);
    }
    asm volatile("cp.async.commit_group;" ::: "memory");
    asm volatile("cp.async.wait_group 0;" ::: "memory");
    __syncthreads();

    uint32_t sA_hi = sbase;
    uint32_t sA_lo = sbase + 16384;
    uint32_t sB_hi = sbase + 32768;
    uint32_t sB_lo = sbase + 49152;

    float acc[4][4][4] = {};
    #pragma unroll
    for (int kt = 0; kt < 4; kt++) {
        uint32_t a_hi[4][4], a_lo[4][4], b_hi[4][2], b_lo[4][2];
        #pragma unroll
        for (int mt = 0; mt < 4; mt++) {
            int row = warpM*64 + mt*16 + (lane & 15);
            uint32_t x = (uint32_t)row*128 + kt*32 + ((lane >> 4)*16);
            uint32_t sw = x ^ ((x >> 3) & 0x70);
            LDSM_X4(a_hi[mt][0], a_hi[mt][1], a_hi[mt][2], a_hi[mt][3], sA_hi + sw);
            LDSM_X4(a_lo[mt][0], a_lo[mt][1], a_lo[mt][2], a_lo[mt][3], sA_lo + sw);
        }
        #pragma unroll
        for (int p = 0; p < 2; p++) {
            int g = lane >> 3;
            int ntile = p*2 + (g >> 1);
            int row = warpN*32 + ntile*8 + (lane & 7);
            uint32_t x = (uint32_t)row*128 + kt*32 + (g & 1)*16;
            uint32_t sw = x ^ ((x >> 3) & 0x70);
            uint32_t r[4];
            LDSM_X4(r[0], r[1], r[2], r[3], sB_hi + sw);
            b_hi[p*2][0] = r[0]; b_hi[p*2][1] = r[1];
            b_hi[p*2+1][0] = r[2]; b_hi[p*2+1][1] = r[3];
            LDSM_X4(r[0], r[1], r[2], r[3], sB_lo + sw);
            b_lo[p*2][0] = r[0]; b_lo[p*2][1] = r[1];
            b_lo[p*2+1][0] = r[2]; b_lo[p*2+1][1] = r[3];
        }
        #pragma unroll
        for (int mt = 0; mt < 4; mt++)
            #pragma unroll
            for (int nn = 0; nn < 4; nn++)
                mma_bf16(acc[mt][nn], a_hi[mt], b_hi[nn]);
        #pragma unroll
        for (int mt = 0; mt < 4; mt++)
            #pragma unroll
            for (int nn = 0; nn < 4; nn++)
                mma_bf16(acc[mt][nn], a_hi[mt], b_lo[nn]);
        #pragma unroll
        for (int mt = 0; mt < 4; mt++)
            #pragma unroll
            for (int nn = 0; nn < 4; nn++)
                mma_bf16(acc[mt][nn], a_lo[mt], b_hi[nn]);
    }
    __syncthreads();

    if (n0 < D_DIM) {
        float* T = (float*)smem;   // 128 x 129
        #pragma unroll
        for (int mt = 0; mt < 4; mt++) {
            int qr = warpM*64 + mt*16 + (lane >> 2);
            #pragma unroll
            for (int nn = 0; nn < 4; nn++) {
                int nc = warpN*32 + nn*8 + (lane & 3)*2;
                float bv0 = b_v[n0 + nc], bv1 = b_v[n0 + nc + 1];
                T[(nc  )*129 + qr    ] = acc[mt][nn][0] + bv0;
                T[(nc+1)*129 + qr    ] = acc[mt][nn][1] + bv1;
                T[(nc  )*129 + qr + 8] = acc[mt][nn][2] + bv0;
                T[(nc+1)*129 + qr + 8] = acc[mt][nn][3] + bv1;
            }
        }
        __syncthreads();

        int sI = m0 / N_DIM;
        int kb = m0 - sI * N_DIM;
        int nt = sI >> 2;
        int j   = tid >> 1, kcl = tid & 1;
        int col = n0 + j;
        int h   = col >> 5, c = col & 31;
        int nr  = ((sI & 3) << 5) + c;
        int kc  = (kb >> 6) + kcl;
        size_t blk = ((size_t)(h*128 + nt)*NKC + kc) * 8192;
        const float* Tr = T + j*129 + kcl*64;
        #pragma unroll
        for (int kk = 0; kk < 64; kk += 2) {
            float f0 = Tr[kk], f1 = Tr[kk+1];
            __nv_bfloat16 h0 = __float2bfloat16(f0);
            __nv_bfloat16 h1 = __float2bfloat16(f1);
            __nv_bfloat162 ph; ph.x = h0; ph.y = h1;
            __nv_bfloat162 pl;
            pl.x = __float2bfloat16(f0 - __bfloat162float(h0));
            pl.y = __float2bfloat16(f1 - __bfloat162float(h1));
            *(__nv_bfloat162*)&g_vh[blk + (size_t)nr*64 + kk] = ph;
            *(__nv_bfloat162*)&g_vl[blk + (size_t)nr*64 + kk] = pl;
        }
    } else {
        int jb = n0 - D_DIM;
        #pragma unroll
        for (int mt = 0; mt < 4; mt++) {
            int row = m0 + warpM*64 + mt*16 + (lane >> 2);
            #pragma unroll
            for (int nn = 0; nn < 4; nn++) {
                int jg = jb + warpN*32 + nn*8 + (lane & 3)*2;
                float bg0 = b_g[jg], bg1 = b_g[jg+1];
                float t0 = acc[mt][nn][0] + bg0, t1 = acc[mt][nn][1] + bg1;
                float t2 = acc[mt][nn][2] + bg0, t3 = acc[mt][nn][3] + bg1;
                *(__half2*)&g_g[(size_t)row*D_DIM + jg] =
                    __floats2half2_rn(1.0f/(1.0f+expf(-t0)), 1.0f/(1.0f+expf(-t1)));
                *(__half2*)&g_g[(size_t)(row+8)*D_DIM + jg] =
                    __floats2half2_rn(1.0f/(1.0f+expf(-t2)), 1.0f/(1.0f+expf(-t3)));
            }
        }
    }
}

// ============================================================
// Kernel 5: attention GEMM via mma.sync bf16 (3-term split)
//   grid reordered: qt fastest -> 3 CTAs sharing a B block are
//   schedule-adjacent -> B served from L2 (604MB -> ~201MB DRAM)
// ============================================================
__global__ __launch_bounds__(256, 1) void k_gemm_att_mma()
{
    extern __shared__ __align__(128) char smem[];
    const uint32_t STAGE = 65536;
    int tid = threadIdx.x;
    int qt = blockIdx.x, nt = blockIdx.y, h = blockIdx.z;
    int wid = tid >> 5, lane = tid & 31;
    int warpM = wid >> 2, warpN = wid & 3;
    uint32_t sbase = smem_u32(smem);

    const char* aHi = (const char*)(g_wh + (size_t)(h*3   + qt) * NKC * 8192);
    const char* aLo = (const char*)(g_wl + (size_t)(h*3   + qt) * NKC * 8192);
    const char* bHi = (const char*)(g_vh + (size_t)(h*128 + nt) * NKC * 8192);
    const char* bLo = (const char*)(g_vl + (size_t)(h*128 + nt) * NKC * 8192);

    float acc[4][4][4] = {};

    auto load_chunk = [&](int kc, int stage){
        size_t cb = (size_t)kc * 16384;
        #pragma unroll
        for (int t = 0; t < 16; t++) {
            int tile = t >> 2;
            int c    = (t & 3) * 256 + tid;
            uint32_t x = (uint32_t)c * 16;
            uint32_t dst = sbase + stage*STAGE + (uint32_t)tile*16384
                         + (x ^ ((x >> 3) & 0x70));
            const char* src = (tile == 0 ? aHi : tile == 1 ? aLo : tile == 2 ? bHi : bLo)
                            + cb + x;
            cpasync16(dst, src);
        }
        asm volatile("cp.async.commit_group;" ::: "memory");
    };

    load_chunk(0, 0);
    for (int kc = 0; kc < NKC; kc++) {
        int stage = kc & 1;
        if (kc < NKC-1) load_chunk(kc+1, stage ^ 1);
        if (kc < NKC-1) asm volatile("cp.async.wait_group 1;" ::: "memory");
        else            asm volatile("cp.async.wait_group 0;" ::: "memory");
        __syncthreads();

        uint32_t sA_hi = sbase + stage*STAGE;
        uint32_t sA_lo = sA_hi + 16384;
        uint32_t sB_hi = sA_hi + 32768;
        uint32_t sB_lo = sA_hi + 49152;

        #pragma unroll
        for (int kt = 0; kt < 4; kt++) {
            uint32_t a_hi[4][4], a_lo[4][4], b_hi[4][2], b_lo[4][2];
            #pragma unroll
            for (int mt = 0; mt < 4; mt++) {
                int row = warpM*64 + mt*16 + (lane & 15);
                uint32_t x = (uint32_t)row*128 + kt*32 + ((lane >> 4)*16);
                uint32_t sw = x ^ ((x >> 3) & 0x70);
                LDSM_X4(a_hi[mt][0], a_hi[mt][1], a_hi[mt][2], a_hi[mt][3], sA_hi + sw);
                LDSM_X4(a_lo[mt][0], a_lo[mt][1], a_lo[mt][2], a_lo[mt][3], sA_lo + sw);
            }
            #pragma unroll
            for (int p = 0; p < 2; p++) {
                int g = lane >> 3;
                int ntile = p*2 + (g >> 1);
                int row = warpN*32 + ntile*8 + (lane & 7);
                uint32_t x = (uint32_t)row*128 + kt*32 + (g & 1)*16;
                uint32_t sw = x ^ ((x >> 3) & 0x70);
                uint32_t r[4];
                LDSM_X4(r[0], r[1], r[2], r[3], sB_hi + sw);
                b_hi[p*2][0] = r[0]; b_hi[p*2][1] = r[1];
                b_hi[p*2+1][0] = r[2]; b_hi[p*2+1][1] = r[3];
                LDSM_X4(r[0], r[1], r[2], r[3], sB_lo + sw);
                b_lo[p*2][0] = r[0]; b_lo[p*2][1] = r[1];
                b_lo[p*2+1][0] = r[2]; b_lo[p*2+1][1] = r[3];
            }
            #pragma unroll
            for (int mt = 0; mt < 4; mt++)
                #pragma unroll
                for (int nn = 0; nn < 4; nn++)
                    mma_bf16(acc[mt][nn], a_hi[mt], b_hi[nn]);
            #pragma unroll
            for (int mt = 0; mt < 4; mt++)
                #pragma unroll
                for (int nn = 0; nn < 4; nn++)
                    mma_bf16(acc[mt][nn], a_hi[mt], b_lo[nn]);
            #pragma unroll
            for (int mt = 0; mt < 4; mt++)
                #pragma unroll
                for (int nn = 0; nn < 4; nn++)
                    mma_bf16(acc[mt][nn], a_lo[mt], b_hi[nn]);
        }
        __syncthreads();
    }

    #pragma unroll
    for (int mt = 0; mt < 4; mt++) {
        int q = qt*128 + warpM*64 + mt*16 + (lane >> 2);
        #pragma unroll
        for (int nn = 0; nn < 4; nn++) {
            int n = nt*128 + warpN*32 + nn*8 + (lane & 3)*2;
            int s = n >> 5, c = n & 31;
            size_t b0 = ((size_t)s*N_DIM + q    )*D_DIM + h*C_DIM + c;
            size_t b1 = ((size_t)s*N_DIM + q + 8)*D_DIM + h*C_DIM + c;
            *(__half2*)&g_o[b0] = __floats2half2_rn(acc[mt][nn][0], acc[mt][nn][1]);
            *(__half2*)&g_o[b1] = __floats2half2_rn(acc[mt][nn][2], acc[mt][nn][3]);
        }
    }
}

// ============================================================
// Kernel 6: output projection via mma.sync fp16 (3-term split)
//   per CTA: M=128, N=64, K=256 (4 chunks of 64)
//   A = (o*g) exact-fp32 product -> split fp16 hi/lo -> smem
//   B = w_o^T pre-split fp16 hi/lo (cp.async)
// ============================================================
__global__ __launch_bounds__(256, 2) void k_gemm_out_mma(const float* __restrict__ b_o,
                                                         float* __restrict__ out)
{
    __shared__ __align__(128) char smem[49152];
    uint32_t sbase = smem_u32(smem);
    uint32_t sAh = sbase, sAl = sbase + 16384, sBh = sbase + 32768, sBl = sbase + 40960;
    int tid = threadIdx.x;
    int m0  = blockIdx.x * 128;
    int wid = tid >> 5, lane = tid & 31;
    int warpM = wid >> 1, warpN = wid & 1;

    float acc[2][4][4] = {};
    int arow = tid >> 1, ahalf = tid & 1;

    for (int k0 = 0; k0 < D_DIM; k0 += 64) {
        // ---- B: cp.async 16KB (hi+lo), swizzled ----
        #pragma unroll
        for (int u = 0; u < 4; u++) {
            int idx = u*256 + tid;              // 0..1023
            int tile = idx >> 9, rem = idx & 511;
            int n = rem >> 3, j = rem & 7;
            uint32_t x = (uint32_t)n*128 + j*16;
            uint32_t dst = (tile ? sBl : sBh) + (x ^ ((x >> 3) & 0x70));
            const __half* src = (tile ? g_wotl : g_woth) + n*256 + k0 + j*8;
            cpasync16(dst, src);
        }
        asm volatile("cp.async.commit_group;" ::: "memory");

        // ---- A: load o,g fp16, exact fp32 product, split fp16 hi/lo ----
        {
            size_t base = (size_t)(m0 + arow)*D_DIM + k0 + ahalf*32;
            uint32_t xb = (uint32_t)arow*128 + ahalf*64;
            #pragma unroll
            for (int u = 0; u < 4; u++) {
                uint4 ov = *(const uint4*)(g_o + base + u*8);
                uint4 gv = *(const uint4*)(g_g + base + u*8);
                const __half2* po = (const __half2*)&ov;
                const __half2* pg = (const __half2*)&gv;
                uint4 hv, lv;
                uint32_t* ph = (uint32_t*)&hv;
                uint32_t* pl = (uint32_t*)&lv;
                #pragma unroll
                for (int j = 0; j < 4; j++) {
                    float2 fo = __half22float2(po[j]);
                    float2 fg = __half22float2(pg[j]);
                    float p0 = fo.x * fg.x, p1 = fo.y * fg.y;
                    __half2 hh = __floats2half2_rn(p0, p1);
                    float2 hf = __half22float2(hh);
                    __half2 ll = __floats2half2_rn(p0 - hf.x, p1 - hf.y);
                    ph[j] = *(uint32_t*)&hh;
                    pl[j] = *(uint32_t*)&ll;
                }
                uint32_t x = xb + u*16;
                uint32_t sw = x ^ ((x >> 3) & 0x70);
                *(uint4*)(smem + sw)         = hv;   // Ah region at offset 0
                *(uint4*)(smem + 16384 + sw) = lv;   // Al region
            }
        }
        asm volatile("cp.async.wait_group 0;" ::: "memory");
        __syncthreads();

        // ---- MMA: 4 k16 steps, 3 terms ----
        #pragma unroll
        for (int kt = 0; kt < 4; kt++) {
            uint32_t a_hi[2][4], a_lo[2][4], b_hi[4][2], b_lo[4][2];
            #pragma unroll
            for (int mt = 0; mt < 2; mt++) {
                int row = warpM*32 + mt*16 + (lane & 15);
                uint32_t x = (uint32_t)row*128 + kt*32 + ((lane >> 4)*16);
                uint32_t sw = x ^ ((x >> 3) & 0x70);
                LDSM_X4(a_hi[mt][0], a_hi[mt][1], a_hi[mt][2], a_hi[mt][3], sAh + sw);
                LDSM_X4(a_lo[mt][0], a_lo[mt][1], a_lo[mt][2], a_lo[mt][3], sAl + sw);
            }
            #pragma unroll
            for (int p = 0; p < 2; p++) {
                int g = lane >> 3;
                int ntile = p*2 + (g >> 1);
                int row = warpN*32 + ntile*8 + (lane & 7);
                uint32_t x = (uint32_t)row*128 + kt*32 + (g & 1)*16;
                uint32_t sw = x ^ ((x >> 3) & 0x70);
                uint32_t r[4];
                LDSM_X4(r[0], r[1], r[2], r[3], sBh + sw);
                b_hi[p*2][0] = r[0]; b_hi[p*2][1] = r[1];
                b_hi[p*2+1][0] = r[2]; b_hi[p*2+1][1] = r[3];
                LDSM_X4(r[0], r[1], r[2], r[3], sBl + sw);
                b_lo[p*2][0] = r[0]; b_lo[p*2][1] = r[1];
                b_lo[p*2+1][0] = r[2]; b_lo[p*2+1][1] = r[3];
            }
            #pragma unroll
            for (int mt = 0; mt < 2; mt++)
                #pragma unroll
                for (int nn = 0; nn < 4; nn++)
                    mma_fp16(acc[mt][nn], a_hi[mt], b_hi[nn]);
            #pragma unroll
            for (int mt = 0; mt < 2; mt++)
                #pragma unroll
                for (int nn = 0; nn < 4; nn++)
                    mma_fp16(acc[mt][nn], a_lo[mt], b_hi[nn]);
            #pragma unroll
            for (int mt = 0; mt < 2; mt++)
                #pragma unroll
                for (int nn = 0; nn < 4; nn++)
                    mma_fp16(acc[mt][nn], a_hi[mt], b_lo[nn]);
        }
        __syncthreads();
    }

    // ---- epilogue: fp32 out = acc + b_o ----
    #pragma unroll
    for (int mt = 0; mt < 2; mt++) {
        int row = m0 + warpM*32 + mt*16 + (lane >> 2);
        #pragma unroll
        for (int nn = 0; nn < 4; nn++) {
            int col = warpN*32 + nn*8 + (lane & 3)*2;
            float b0 = b_o[col], b1 = b_o[col+1];
            *(float2*)(out + (size_t)row*CIN + col) =
                make_float2(acc[mt][nn][0] + b0, acc[mt][nn][1] + b1);
            *(float2*)(out + (size_t)(row+8)*CIN + col) =
                make_float2(acc[mt][nn][2] + b0, acc[mt][nn][3] + b1);
        }
    }
}

// ============================================================
extern "C" void kernel_launch(void* const* d_in, const int* in_sizes, int n_in,
                              void* d_out, int out_size)
{
    const float* m       = (const float*)d_in[0];
    const float* z       = (const float*)d_in[1];
    const float* mask    = (const float*)d_in[2];
    const float* gamma_m = (const float*)d_in[3];
    const float* beta_m  = (const float*)d_in[4];
    const float* gamma_z = (const float*)d_in[5];
    const float* beta_z  = (const float*)d_in[6];
    const float* w_z     = (const float*)d_in[7];
    const float* b_z     = (const float*)d_in[8];
    const float* w_v     = (const float*)d_in[9];
    const float* b_v     = (const float*)d_in[10];
    const float* w_g     = (const float*)d_in[11];
    const float* b_g     = (const float*)d_in[12];
    const float* w_o     = (const float*)d_in[13];
    const float* b_o     = (const float*)d_in[14];
    float* out = (float*)d_out;

    cudaFuncSetAttribute(k_gemm_att_mma, cudaFuncAttributeMaxDynamicSharedMemorySize, 131072);
    cudaFuncSetAttribute(k_gemm_vg_mma,  cudaFuncAttributeMaxDynamicSharedMemorySize, 66048);

    k_prep_w<<<512, 64>>>(w_v, w_g);
    k_prep_wo<<<64, 256>>>(w_o);
    k_lnz_logits<<<(N_DIM*N_DIM)/8, 256>>>(z, mask, gamma_z, beta_z, w_z, b_z);
    k_softmax<<<H_DIM*N_DIM, 128>>>();
    k_lnm<<<MROWS/8, 256>>>(m, gamma_m, beta_m);
    k_gemm_vg_mma<<<dim3(4, MROWS/128), 256, 66048>>>(b_v, b_g);
    k_gemm_att_mma<<<dim3(3, 128, 8), 256, 131072>>>();
    k_gemm_out_mma<<<MROWS/128, 256>>>(b_o, out);
}